// round 12
// baseline (speedup 1.0000x reference)
#include <cuda_runtime.h>
#include <cuda_bf16.h>
#include <cstdint>

#define ENC_DIM 1024
#define TOK_DIM 4096
#define NB 8
#define NT 3000
#define M_TOTAL 4096
#define FRATE 50.0f
#define LN_EPS 1e-5f

// ---------------- HMMA GEMM tiling ----------------
#define BM 128
#define BN 128
#define BK 64                       // bf16 per chunk (4 k16 MMA steps, one 128B block)
#define PADK 72                     // padded row length (bf16) -> 144B rows (36w = 4 mod 32)
#define ROWB2 (PADK * 2)            // 144
#define A_STAGE (BM * ROWB2)        // 18432 B
#define B_STAGE (BN * ROWB2)        // 18432 B
#define HG_SMEM (2 * (A_STAGE + B_STAGE))   // 73728 B/CTA -> 2 CTAs/SM
#define NCH_TOT (3 * (ENC_DIM / BK))        // 48 chunks (3 plane pairs x 16)

// ---------------- scratch (bf16 planes stored k-block-PERMUTED) ----------------
// Within each 128B k-block (32 words), logical word (8ks + 4h + t) lives at
// physical position (t*8 + 2ks + h).  Fragment consumers then read 8 contiguous
// words per (thread, row) -> two LDS.128.
__device__ __nv_bfloat16 g_a_hi[(size_t)M_TOTAL * ENC_DIM];
__device__ __nv_bfloat16 g_a_lo[(size_t)M_TOTAL * ENC_DIM];
__device__ __nv_bfloat16 g_b_hi[(size_t)TOK_DIM * ENC_DIM];
__device__ __nv_bfloat16 g_b_lo[(size_t)TOK_DIM * ENC_DIM];
__device__ float g_h[(size_t)M_TOTAL * TOK_DIM];

// ---------------- helpers ----------------
__device__ __forceinline__ uint32_t smem_u32(const void* p) {
    uint32_t r;
    asm("{ .reg .u64 t; cvta.to.shared.u64 t, %1; cvt.u32.u64 %0, t; }" : "=r"(r) : "l"(p));
    return r;
}
__device__ __forceinline__ void cp_async16(uint32_t s, const void* g) {
    asm volatile("cp.async.cg.shared.global [%0], [%1], 16;" :: "r"(s), "l"(g) : "memory");
}
__device__ __forceinline__ void mma16816(float* d, const uint32_t* a, const uint32_t* b) {
    asm volatile(
        "mma.sync.aligned.m16n8k16.row.col.f32.bf16.bf16.f32 "
        "{%0,%1,%2,%3}, {%4,%5,%6,%7}, {%8,%9}, {%0,%1,%2,%3};"
        : "+f"(d[0]), "+f"(d[1]), "+f"(d[2]), "+f"(d[3])
        : "r"(a[0]), "r"(a[1]), "r"(a[2]), "r"(a[3]), "r"(b[0]), "r"(b[1]));
}
__device__ __forceinline__ void split_bf16(float x, __nv_bfloat16& hi, __nv_bfloat16& lo) {
    hi = __float2bfloat16(x);
    lo = __float2bfloat16(x - __bfloat162float(hi));
}
__device__ __forceinline__ int perm_word(int W) {     // logical 0..31 -> physical
    const int ks = W >> 3, r = W & 7;
    return (r & 3) * 8 + ks * 2 + (r >> 2);
}
__device__ __forceinline__ uint32_t pack_bf2(__nv_bfloat16 e0, __nv_bfloat16 e1) {
    const uint16_t a = *(const uint16_t*)&e0, b = *(const uint16_t*)&e1;
    return (uint32_t)a | ((uint32_t)b << 16);         // low half = even element
}

// ---------------- kernel 1: ragged mean-pool -> permuted bf16 hi/lo planes -----
__global__ void __launch_bounds__(256) pool_kernel(const float* __restrict__ x,
                                                   const float* __restrict__ ts) {
    const int tok = blockIdx.x;
    const int b   = tok >> 9;
    const int t   = threadIdx.x;                      // handles elems 4t..4t+3
    const float2 tt = ((const float2*)ts)[tok];
    int s = (int)floorf(tt.x * FRATE);
    int e = (int)floorf(tt.y * FRATE);
    if (e < s + 1) e = s + 1;
    if (e > NT) e = NT;
    const float4* xb = (const float4*)(x + (size_t)b * NT * ENC_DIM);
    float4 acc = make_float4(0.f, 0.f, 0.f, 0.f);
    for (int f = s; f < e; f++) {
        float4 v = xb[(size_t)f * (ENC_DIM / 4) + t];
        acc.x += v.x; acc.y += v.y; acc.z += v.z; acc.w += v.w;
    }
    const float inv = 1.f / (float)(e - s);
    float m[4] = {acc.x * inv, acc.y * inv, acc.z * inv, acc.w * inv};
    __nv_bfloat16 hi[4], lo[4];
    #pragma unroll
    for (int i = 0; i < 4; i++) split_bf16(m[i], hi[i], lo[i]);
    // permuted store: words Wl, Wl+1 of block (t>>4)
    const int Wl = (t & 15) * 2;
    const int p0 = perm_word(Wl), p1 = perm_word(Wl + 1);
    const size_t wbase = (size_t)tok * (ENC_DIM / 2) + (t >> 4) * 32;
    uint32_t* dh = (uint32_t*)g_a_hi + wbase;
    uint32_t* dl = (uint32_t*)g_a_lo + wbase;
    dh[p0] = pack_bf2(hi[0], hi[1]); dh[p1] = pack_bf2(hi[2], hi[3]);
    dl[p0] = pack_bf2(lo[0], lo[1]); dl[p1] = pack_bf2(lo[2], lo[3]);
}

// ---------------- kernel 2: W -> permuted bf16 hi/lo planes ----------------
__global__ void __launch_bounds__(256) wsplit_kernel(const float* __restrict__ W) {
    const size_t idx = (size_t)blockIdx.x * 256 + threadIdx.x;
    const size_t e0 = idx * 4;
    float4 v = *(const float4*)(W + e0);
    __nv_bfloat16 hi[4], lo[4];
    split_bf16(v.x, hi[0], lo[0]); split_bf16(v.y, hi[1], lo[1]);
    split_bf16(v.z, hi[2], lo[2]); split_bf16(v.w, hi[3], lo[3]);
    const size_t g0 = e0 >> 1;                        // logical word index
    const size_t base = g0 & ~(size_t)31;
    const int Wl = (int)(g0 & 31);
    const int p0 = perm_word(Wl), p1 = perm_word(Wl + 1);
    uint32_t* dh = (uint32_t*)g_b_hi + base;
    uint32_t* dl = (uint32_t*)g_b_lo + base;
    dh[p0] = pack_bf2(hi[0], hi[1]); dh[p1] = pack_bf2(hi[2], hi[3]);
    dl[p0] = pack_bf2(lo[0], lo[1]); dl[p1] = pack_bf2(lo[2], lo[3]);
}

// ---------------- kernel 3: mma.sync bf16 split GEMM + bias + relu ----------------
// Tile 128x128, warp tile 64x32, 2 CTAs/SM, BK=64; fragments via LDS.128
// from the pre-permuted layout (24 LDS.128 per warp-chunk vs 96 LDS.32).
__global__ void __launch_bounds__(256, 2) hgemm_kernel(const float* __restrict__ bias) {
    extern __shared__ __align__(16) char dsm[];
    const int tid  = threadIdx.x;
    const int wid  = tid >> 5;
    const int lane = tid & 31;
    const int g    = lane >> 2;          // 0..7
    const int t    = lane & 3;           // 0..3
    const int wm   = wid >> 2;           // 0..1 (m half)
    const int wn   = wid & 3;            // 0..3 (n quarter)
    const int m0 = blockIdx.y * BM;
    const int n0 = blockIdx.x * BN;

    const uint32_t smem0 = smem_u32(dsm);

    const __nv_bfloat16* Apl[3] = {g_a_hi, g_a_hi, g_a_lo};
    const __nv_bfloat16* Bpl[3] = {g_b_hi, g_b_lo, g_b_hi};

    float acc[4][4][4];
    #pragma unroll
    for (int i = 0; i < 4; i++)
        #pragma unroll
        for (int j = 0; j < 4; j++)
            #pragma unroll
            for (int q = 0; q < 4; q++) acc[i][j][q] = 0.f;

    // loader: per operand 128 rows x 128B = 1024 x 16B segs; thread does 4 per operand
    auto load_chunk = [&](int c, int buf) {
        const int p  = c >> 4;                       // plane pair (16 chunks each)
        const int ko = (c & 15) * BK;                // element offset (block-aligned)
        #pragma unroll
        for (int h = 0; h < 4; h++) {
            const int seg = tid + h * 256;
            const int row = seg >> 3;
            const int off = (seg & 7) * 16;          // byte offset in 128B payload
            const __nv_bfloat16* Ab = Apl[p] + (size_t)(m0 + row) * ENC_DIM + ko;
            cp_async16(smem0 + buf * A_STAGE + row * ROWB2 + off, (const char*)Ab + off);
            const __nv_bfloat16* Bb = Bpl[p] + (size_t)(n0 + row) * ENC_DIM + ko;
            cp_async16(smem0 + 2 * A_STAGE + buf * B_STAGE + row * ROWB2 + off,
                       (const char*)Bb + off);
        }
    };

    load_chunk(0, 0);
    asm volatile("cp.async.commit_group;" ::: "memory");

    const int tb = t * 32;                           // thread's byte base in a row
    int buf = 0;
    for (int c = 0; c < NCH_TOT; c++) {
        if (c + 1 < NCH_TOT) load_chunk(c + 1, buf ^ 1);
        asm volatile("cp.async.commit_group;" ::: "memory");
        asm volatile("cp.async.wait_group 1;" ::: "memory");
        __syncthreads();

        const char* sAb = dsm + buf * A_STAGE;
        const char* sBb = dsm + 2 * A_STAGE + buf * B_STAGE;
        #pragma unroll
        for (int pair = 0; pair < 2; pair++) {       // (ks0,ks1) then (ks2,ks3)
            const int pb = tb + pair * 16;
            uint4 bw[4];
            #pragma unroll
            for (int j = 0; j < 4; j++) {
                const int r = wn * 32 + j * 8 + g;
                bw[j] = *(const uint4*)(sBb + r * ROWB2 + pb);
            }
            #pragma unroll
            for (int i = 0; i < 4; i++) {
                const int r = wm * 64 + i * 16 + g;
                const uint4 awA = *(const uint4*)(sAb + r * ROWB2 + pb);
                const uint4 awB = *(const uint4*)(sAb + (r + 8) * ROWB2 + pb);
                {   // ksl = 0
                    const uint32_t a4[4] = {awA.x, awB.x, awA.y, awB.y};
                    #pragma unroll
                    for (int j = 0; j < 4; j++) {
                        const uint32_t b2[2] = {bw[j].x, bw[j].y};
                        mma16816(acc[i][j], a4, b2);
                    }
                }
                {   // ksl = 1
                    const uint32_t a4[4] = {awA.z, awB.z, awA.w, awB.w};
                    #pragma unroll
                    for (int j = 0; j < 4; j++) {
                        const uint32_t b2[2] = {bw[j].z, bw[j].w};
                        mma16816(acc[i][j], a4, b2);
                    }
                }
            }
        }
        __syncthreads();
        buf ^= 1;
    }

    // epilogue: bias + relu -> g_h
    #pragma unroll
    for (int j = 0; j < 4; j++) {
        const int cb = n0 + wn * 32 + j * 8 + t * 2;
        const float2 bv = *(const float2*)(bias + cb);
        #pragma unroll
        for (int i = 0; i < 4; i++) {
            const int r0 = m0 + wm * 64 + i * 16 + g;
            float2 o0, o1;
            o0.x = fmaxf(acc[i][j][0] + bv.x, 0.f);
            o0.y = fmaxf(acc[i][j][1] + bv.y, 0.f);
            o1.x = fmaxf(acc[i][j][2] + bv.x, 0.f);
            o1.y = fmaxf(acc[i][j][3] + bv.y, 0.f);
            *(float2*)(g_h + (size_t)r0 * TOK_DIM + cb)       = o0;
            *(float2*)(g_h + (size_t)(r0 + 8) * TOK_DIM + cb) = o1;
        }
    }
}

// ---------------- kernel 4: LayerNorm over 4096 -> out ----------------
__global__ void __launch_bounds__(256) ln_kernel(const float* __restrict__ gamma,
                                                 const float* __restrict__ beta,
                                                 float* __restrict__ out) {
    const int rowid = blockIdx.x;
    const int t = threadIdx.x;
    const float4* h4 = (const float4*)(g_h + (size_t)rowid * TOK_DIM);
    float4 v[4];
    float sum = 0.f;
    #pragma unroll
    for (int i = 0; i < 4; i++) {
        v[i] = h4[i * 256 + t];
        sum += v[i].x + v[i].y + v[i].z + v[i].w;
    }
    __shared__ float red1[8], red2[8];
    #pragma unroll
    for (int o = 16; o > 0; o >>= 1) sum += __shfl_xor_sync(0xffffffffu, sum, o);
    if ((t & 31) == 0) red1[t >> 5] = sum;
    __syncthreads();
    float tot = 0.f;
    #pragma unroll
    for (int i = 0; i < 8; i++) tot += red1[i];
    const float mu = tot * (1.f / TOK_DIM);

    float sq = 0.f;
    #pragma unroll
    for (int i = 0; i < 4; i++) {
        float dx = v[i].x - mu, dy = v[i].y - mu, dz = v[i].z - mu, dw = v[i].w - mu;
        sq += dx * dx + dy * dy + dz * dz + dw * dw;
    }
    #pragma unroll
    for (int o = 16; o > 0; o >>= 1) sq += __shfl_xor_sync(0xffffffffu, sq, o);
    if ((t & 31) == 0) red2[t >> 5] = sq;
    __syncthreads();
    float tot2 = 0.f;
    #pragma unroll
    for (int i = 0; i < 8; i++) tot2 += red2[i];
    const float rstd = 1.f / sqrtf(tot2 * (1.f / TOK_DIM) + LN_EPS);

    const float4* g4 = (const float4*)gamma;
    const float4* b4 = (const float4*)beta;
    float4* o4 = (float4*)(out + (size_t)rowid * TOK_DIM);
    #pragma unroll
    for (int i = 0; i < 4; i++) {
        const int idx = i * 256 + t;
        const float4 gv = g4[idx], bv = b4[idx];
        float4 r;
        r.x = (v[i].x - mu) * rstd * gv.x + bv.x;
        r.y = (v[i].y - mu) * rstd * gv.y + bv.y;
        r.z = (v[i].z - mu) * rstd * gv.z + bv.z;
        r.w = (v[i].w - mu) * rstd * gv.w + bv.w;
        o4[idx] = r;
    }
}

// ---------------- launcher ----------------
extern "C" void kernel_launch(void* const* d_in, const int* in_sizes, int n_in,
                              void* d_out, int out_size) {
    const float* x     = (const float*)d_in[0];
    const float* ts    = (const float*)d_in[1];
    const float* W     = (const float*)d_in[2];
    const float* b     = (const float*)d_in[3];
    const float* gamma = (const float*)d_in[4];
    const float* beta  = (const float*)d_in[5];
    float* out = (float*)d_out;

    cudaFuncSetAttribute(hgemm_kernel, cudaFuncAttributeMaxDynamicSharedMemorySize, HG_SMEM);

    pool_kernel<<<M_TOTAL, 256>>>(x, ts);
    wsplit_kernel<<<(TOK_DIM * ENC_DIM) / 1024, 256>>>(W);
    dim3 gg(TOK_DIM / BN, M_TOTAL / BM);          // 32 x 32
    hgemm_kernel<<<gg, 256, HG_SMEM>>>(b);
    ln_kernel<<<M_TOTAL, 256>>>(gamma, beta, out);
}